// round 1
// baseline (speedup 1.0000x reference)
#include <cuda_runtime.h>
#include <cuda_bf16.h>

// Implicit-GEMM fp32 conv: M=Co=512, N=B*54*54=93312, K=Ci*9=2304.
// BM=128, BN=128, BK=8, 256 threads, 8x8 micro-tile per thread using
// packed fma.rn.f32x2 (FFMA2) with interleaved (2ty+32p / 2tx+32q) mapping
// for conflict-free LDS.64 fragment reads.

#define KTOT   2304
#define KITERS 288          // KTOT / 8
#define CIN    256
#define HWIN   56
#define XIMG   (CIN * HWIN * HWIN)   // 802816
#define NPIMG  2916                  // 54*54
#define OUTIMG (512 * NPIMG)         // 1492992

__device__ __forceinline__ unsigned long long pack2(float lo, float hi) {
    unsigned long long r;
    asm("mov.b64 %0, {%1, %2};" : "=l"(r) : "f"(lo), "f"(hi));
    return r;
}
__device__ __forceinline__ void unpack2(unsigned long long v, float& lo, float& hi) {
    asm("mov.b64 {%0, %1}, %2;" : "=f"(lo), "=f"(hi) : "l"(v));
}
__device__ __forceinline__ void ffma2(unsigned long long& d,
                                      unsigned long long a,
                                      unsigned long long b) {
    // d.lo = a.lo*b.lo + d.lo ; d.hi = a.hi*b.hi + d.hi
    asm("fma.rn.f32x2 %0, %1, %2, %0;" : "+l"(d) : "l"(a), "l"(b));
}

__global__ void __launch_bounds__(256, 2)
conv_gemm_f32x2(const float* __restrict__ x,
                const float* __restrict__ w,
                float* __restrict__ out)
{
    __shared__ float As[8][132];   // [k][m], padded to 132 -> conflict-free stores
    __shared__ float Bs[8][128];   // [k][n]

    const int tid = threadIdx.x;
    const int tx  = tid & 15;      // 0..15 -> column pairs
    const int ty  = tid >> 4;      // 0..15 -> row pairs
    const int bn  = blockIdx.x;    // 0..728
    const int bm  = blockIdx.y;    // 0..3

    // ---- A (weight) global-load mapping: thread -> (k = tid&7, m = tid>>3 + 32r)
    const int ka = tid & 7;
    const int ma = tid >> 3;                   // 0..31
    const float* wp = w + (size_t)(bm * 128 + ma) * KTOT + ka;

    // ---- B (im2col x) global-load mapping: thread -> (k = (tid>>7) + 2r, n = tid&127)
    const int kb = tid >> 7;                   // 0 or 1
    const int nb = tid & 127;
    const int ng = bn * 128 + nb;              // global pixel index
    const int bimg = ng / NPIMG;
    const int prem = ng - bimg * NPIMG;
    const int oh = prem / 54;
    const int ow = prem - oh * 54;
    const float* xp = x + (size_t)bimg * XIMG + oh * HWIN + ow;

    float aReg[4], bReg[4];

    // ---- prologue: tile kt = 0
    #pragma unroll
    for (int r = 0; r < 4; ++r)
        aReg[r] = wp[(size_t)(32 * r) * KTOT];
    #pragma unroll
    for (int r = 0; r < 4; ++r) {
        int kg = kb + 2 * r;
        int ci = kg / 9;
        int k9 = kg - ci * 9;
        int kh = k9 / 3;
        int kw = k9 - kh * 3;
        bReg[r] = xp[ci * 3136 + kh * HWIN + kw];
    }
    #pragma unroll
    for (int r = 0; r < 4; ++r) As[ka][ma + 32 * r] = aReg[r];
    #pragma unroll
    for (int r = 0; r < 4; ++r) Bs[kb + 2 * r][nb] = bReg[r];
    __syncthreads();

    unsigned long long acc[8][4];
    #pragma unroll
    for (int i = 0; i < 8; ++i)
        #pragma unroll
        for (int q = 0; q < 4; ++q)
            acc[i][q] = 0ULL;

    // ---- main loop, software pipelined
    for (int kt = 1; kt <= KITERS; ++kt) {
        if (kt < KITERS) {
            const float* wpk = wp + kt * 8;
            #pragma unroll
            for (int r = 0; r < 4; ++r)
                aReg[r] = wpk[(size_t)(32 * r) * KTOT];
            #pragma unroll
            for (int r = 0; r < 4; ++r) {
                int kg = kt * 8 + kb + 2 * r;
                int ci = kg / 9;
                int k9 = kg - ci * 9;
                int kh = k9 / 3;
                int kw = k9 - kh * 3;
                bReg[r] = xp[ci * 3136 + kh * HWIN + kw];
            }
        }

        #pragma unroll
        for (int kk = 0; kk < 8; ++kk) {
            unsigned long long ar[8], bq[4];
            #pragma unroll
            for (int p = 0; p < 4; ++p) {
                float2 a = *(const float2*)&As[kk][2 * ty + 32 * p];
                ar[2 * p + 0] = pack2(a.x, a.x);
                ar[2 * p + 1] = pack2(a.y, a.y);
            }
            #pragma unroll
            for (int q = 0; q < 4; ++q)
                bq[q] = *(const unsigned long long*)&Bs[kk][2 * tx + 32 * q];
            #pragma unroll
            for (int i = 0; i < 8; ++i)
                #pragma unroll
                for (int q = 0; q < 4; ++q)
                    ffma2(acc[i][q], ar[i], bq[q]);
        }
        __syncthreads();

        if (kt < KITERS) {
            #pragma unroll
            for (int r = 0; r < 4; ++r) As[ka][ma + 32 * r] = aReg[r];
            #pragma unroll
            for (int r = 0; r < 4; ++r) Bs[kb + 2 * r][nb] = bReg[r];
            __syncthreads();
        }
    }

    // ---- epilogue: out[b][co][oh][ow]; n-pairs are contiguous and never
    // cross an image boundary (pairs start even, NPIMG even) -> float2 stores.
    #pragma unroll
    for (int q = 0; q < 4; ++q) {
        int n = bn * 128 + 2 * tx + 32 * q;
        int b = n / NPIMG;
        int rr = n - b * NPIMG;
        float* op = out + (size_t)b * OUTIMG + rr;
        #pragma unroll
        for (int i = 0; i < 8; ++i) {
            int co = bm * 128 + 2 * ty + 32 * (i >> 1) + (i & 1);
            float lo, hi;
            unpack2(acc[i][q], lo, hi);
            *(float2*)(op + (size_t)co * NPIMG) = make_float2(lo, hi);
        }
    }
}

extern "C" void kernel_launch(void* const* d_in, const int* in_sizes, int n_in,
                              void* d_out, int out_size)
{
    const float* x = (const float*)d_in[0];   // [32,256,56,56]
    const float* w = (const float*)d_in[1];   // [512,256,3,3]
    float* out = (float*)d_out;               // [32,512,54,54]

    dim3 grid(729, 4);   // N-tiles (93312/128) x M-tiles (512/128)
    conv_gemm_f32x2<<<grid, 256>>>(x, w, out);
}

// round 3
// speedup vs baseline: 2.4411x; 2.4411x over previous
#include <cuda_runtime.h>
#include <cuda_bf16.h>
#include <cstdint>

// ============================================================================
// Split-bf16 mma.sync (HMMA) implicit-GEMM conv for plain sm_103 target.
// D[512, 93312] = W[512, 2304] * im2col(X)[2304, 93312], fp32 accum in regs.
// fp32 = hi(bf16) + lo(bf16); 3 MMAs per k-step: ah*bh + ah*bl + al*bh.
// CTA 128x128, BK=32 double-buffered, 8 warps (2x4), warp tile 64x32.
// ============================================================================

#define KTOT   2304
#define KITERS 72            // 2304 / 32
#define NPIMG  2916          // 54*54
#define OUTIMG (512*NPIMG)
#define XIMG   (256*3136)

// dynamic smem layout
#define BUF_STRIDE 32768
#define OFF_AHI 0            // 128 rows x 64B
#define OFF_ALO 8192
#define OFF_BHI 16384
#define OFF_BLO 24576
#define OFF_KOFF 65536                    // after 2 buffers
#define SMEM_BYTES (OFF_KOFF + KTOT*4)    // 74752

// Packed {hi,lo} bf16 operands, produced once per launch.
__device__ __nv_bfloat162 g_wpack[512 * KTOT];          // 4.7 MB
__device__ __nv_bfloat162 g_xpack[32 * 256 * 56 * 56];  // 103 MB

// ---------------------------------------------------------------------------
__device__ __forceinline__ uint32_t smem_u32(const void* p) {
    uint32_t a;
    asm("{ .reg .u64 t; cvta.to.shared.u64 t, %1; cvt.u32.u64 %0, t; }"
        : "=r"(a) : "l"(p));
    return a;
}
__device__ __forceinline__ void sts64(uint32_t addr, uint32_t a, uint32_t b) {
    asm volatile("st.shared.v2.b32 [%0], {%1, %2};" :: "r"(addr), "r"(a), "r"(b));
}
__device__ __forceinline__ void ldsm4(uint32_t a, uint32_t& r0, uint32_t& r1,
                                      uint32_t& r2, uint32_t& r3) {
    asm volatile("ldmatrix.sync.aligned.m8n8.x4.shared.b16 {%0,%1,%2,%3}, [%4];"
                 : "=r"(r0), "=r"(r1), "=r"(r2), "=r"(r3) : "r"(a));
}
__device__ __forceinline__ void mma_bf16(float* c, const uint32_t* a,
                                         uint32_t b0, uint32_t b1) {
    asm volatile(
        "mma.sync.aligned.m16n8k16.row.col.f32.bf16.bf16.f32 "
        "{%0,%1,%2,%3}, {%4,%5,%6,%7}, {%8,%9}, {%0,%1,%2,%3};"
        : "+f"(c[0]), "+f"(c[1]), "+f"(c[2]), "+f"(c[3])
        : "r"(a[0]), "r"(a[1]), "r"(a[2]), "r"(a[3]), "r"(b0), "r"(b1));
}

// ---------------------------------------------------------------------------
// pack kernels: fp32 -> {hi, lo} bf16x2 (u32 = lo<<16 | hi)
// ---------------------------------------------------------------------------
__device__ __forceinline__ uint32_t pack_hl(float v) {
    __nv_bfloat16 hi = __float2bfloat16_rn(v);
    float r = v - __bfloat162float(hi);
    __nv_bfloat16 lo = __float2bfloat16_rn(r);
    __nv_bfloat162 p; p.x = hi; p.y = lo;
    return *reinterpret_cast<uint32_t*>(&p);
}
__global__ void pack_x_kernel(const float* __restrict__ x) {
    int i = blockIdx.x * blockDim.x + threadIdx.x;   // 6422528 total
    float4 v = ((const float4*)x)[i];
    ((uint4*)g_xpack)[i] = make_uint4(pack_hl(v.x), pack_hl(v.y),
                                      pack_hl(v.z), pack_hl(v.w));
}
__global__ void pack_w_kernel(const float* __restrict__ w) {
    int i = blockIdx.x * blockDim.x + threadIdx.x;   // 294912 total
    float4 v = ((const float4*)w)[i];
    ((uint4*)g_wpack)[i] = make_uint4(pack_hl(v.x), pack_hl(v.y),
                                      pack_hl(v.z), pack_hl(v.w));
}

// ---------------------------------------------------------------------------
// producer: one 32-k chunk into one buffer. thread -> (row = tid>>1, khalf)
// smem element (row, k): byte = row*64 + ((2k) ^ (((row>>1)&3)<<4))
// ---------------------------------------------------------------------------
__device__ __forceinline__ void produce_chunk(
    int ch, uint32_t bufb, const uint4* wp4, const __nv_bfloat162* xb,
    uint32_t koffs, int prow, int khalf, uint32_t pswz)
{
    uint4 av[4];
    {
        const uint4* ap = wp4 + ch * 8 + khalf * 4;
        #pragma unroll
        for (int j = 0; j < 4; ++j) av[j] = ap[j];
    }
    uint32_t bx[16];
    {
        const uint32_t kb4 = koffs + (uint32_t)(ch * 32 + khalf * 16) * 4;
        #pragma unroll
        for (int g = 0; g < 4; ++g) {
            uint32_t k0, k1, k2, k3;
            asm volatile("ld.shared.v4.b32 {%0,%1,%2,%3}, [%4];"
                         : "=r"(k0), "=r"(k1), "=r"(k2), "=r"(k3)
                         : "r"(kb4 + g * 16));
            bx[4*g+0] = *(const uint32_t*)(xb + k0);
            bx[4*g+1] = *(const uint32_t*)(xb + k1);
            bx[4*g+2] = *(const uint32_t*)(xb + k2);
            bx[4*g+3] = *(const uint32_t*)(xb + k3);
        }
    }
    const uint32_t sA = bufb + (uint32_t)prow * 64;
    const uint32_t sB = sA + OFF_BHI;
    const uint32_t kobase = (uint32_t)khalf * 32;
    #pragma unroll
    for (int j = 0; j < 4; ++j) {
        uint32_t h0 = __byte_perm(av[j].x, av[j].y, 0x5410);
        uint32_t h1 = __byte_perm(av[j].z, av[j].w, 0x5410);
        uint32_t l0 = __byte_perm(av[j].x, av[j].y, 0x7632);
        uint32_t l1 = __byte_perm(av[j].z, av[j].w, 0x7632);
        uint32_t ko = (kobase + 8u * j) ^ pswz;
        sts64(sA + ko, h0, h1);
        sts64(sA + 8192 + ko, l0, l1);
    }
    #pragma unroll
    for (int g = 0; g < 4; ++g) {
        uint32_t h0 = __byte_perm(bx[4*g+0], bx[4*g+1], 0x5410);
        uint32_t h1 = __byte_perm(bx[4*g+2], bx[4*g+3], 0x5410);
        uint32_t l0 = __byte_perm(bx[4*g+0], bx[4*g+1], 0x7632);
        uint32_t l1 = __byte_perm(bx[4*g+2], bx[4*g+3], 0x7632);
        uint32_t ko = (kobase + 8u * g) ^ pswz;
        sts64(sB + ko, h0, h1);
        sts64(sB + 8192 + ko, l0, l1);
    }
}

// ---------------------------------------------------------------------------
__device__ __forceinline__ void mma_chunk(
    uint32_t bufb, float (&acc)[4][4][4],
    uint32_t aRowOff, uint32_t aKext, uint32_t aSwz,
    uint32_t bRowOff, uint32_t bKext, uint32_t bSwz)
{
    #pragma unroll
    for (int kb = 0; kb < 2; ++kb) {
        const uint32_t kb2 = (uint32_t)kb * 32;
        const uint32_t aK = (kb2 + aKext) ^ aSwz;
        const uint32_t bK = (kb2 + bKext) ^ bSwz;

        uint32_t bh[8], bl[8];
        const uint32_t bAddr = bufb + OFF_BHI + bRowOff + bK;
        ldsm4(bAddr,               bh[0], bh[1], bh[2], bh[3]);
        ldsm4(bAddr + 1024,        bh[4], bh[5], bh[6], bh[7]);
        ldsm4(bAddr + 8192,        bl[0], bl[1], bl[2], bl[3]);
        ldsm4(bAddr + 8192 + 1024, bl[4], bl[5], bl[6], bl[7]);

        uint32_t a[16];
        const uint32_t aAddr = bufb + aRowOff + aK;
        #pragma unroll
        for (int am = 0; am < 4; ++am)
            ldsm4(aAddr + am * 1024, a[4*am], a[4*am+1], a[4*am+2], a[4*am+3]);

        #pragma unroll
        for (int am = 0; am < 4; ++am)
            #pragma unroll
            for (int an = 0; an < 4; ++an) {
                mma_bf16(acc[am][an], a + 4*am, bh[2*an], bh[2*an+1]);
                mma_bf16(acc[am][an], a + 4*am, bl[2*an], bl[2*an+1]);
            }

        #pragma unroll
        for (int am = 0; am < 4; ++am)
            ldsm4(aAddr + 8192 + am * 1024, a[4*am], a[4*am+1], a[4*am+2], a[4*am+3]);

        #pragma unroll
        for (int am = 0; am < 4; ++am)
            #pragma unroll
            for (int an = 0; an < 4; ++an)
                mma_bf16(acc[am][an], a + 4*am, bh[2*an], bh[2*an+1]);
    }
}

// ---------------------------------------------------------------------------
__global__ void __launch_bounds__(256, 2)
conv_mma_kernel(float* __restrict__ out)
{
    extern __shared__ char smem[];
    const uint32_t sb = smem_u32(smem);
    const int tid = threadIdx.x;
    const int bn = blockIdx.x, bm = blockIdx.y;

    // im2col k -> x-offset table
    for (int k = tid; k < KTOT; k += 256) {
        int ci = k / 9, r9 = k - ci * 9;
        int kh = r9 / 3, kw = r9 - kh * 3;
        *(uint32_t*)(smem + OFF_KOFF + k * 4) = (uint32_t)(ci * 3136 + kh * 56 + kw);
    }

    // producer invariants
    const int prow = tid >> 1, khalf = tid & 1;
    const uint4* wp4 = (const uint4*)(g_wpack + (size_t)(bm * 128 + prow) * KTOT);
    const int ng = bn * 128 + prow;
    const int bimg = ng / NPIMG;
    const int prem = ng - bimg * NPIMG;
    const int oh = prem / 54, ow = prem - oh * 54;
    const __nv_bfloat162* xb = g_xpack + (size_t)bimg * XIMG + oh * 56 + ow;
    const uint32_t pswz = (uint32_t)((prow >> 1) & 3) << 4;
    const uint32_t koffs = sb + OFF_KOFF;

    // mma invariants: warp grid 2(m) x 4(n)
    const int lane = tid & 31, wid = tid >> 5;
    const int wm = wid & 1, wn = wid >> 1;
    const uint32_t aRowOff = (uint32_t)(wm * 64 + (lane & 15)) * 64;
    const uint32_t aKext   = (uint32_t)(lane >> 4) << 4;
    const uint32_t aSwz    = (uint32_t)(((lane & 15) >> 1) & 3) << 4;
    const uint32_t bRowOff = (uint32_t)(wn * 32 + (lane & 7) + ((lane >> 4) << 3)) * 64;
    const uint32_t bKext   = (uint32_t)((lane >> 3) & 1) << 4;
    const uint32_t bSwz    = (uint32_t)(((lane & 7) >> 1) & 3) << 4;

    float acc[4][4][4];
    #pragma unroll
    for (int i = 0; i < 4; ++i)
        #pragma unroll
        for (int j = 0; j < 4; ++j)
            #pragma unroll
            for (int r = 0; r < 4; ++r) acc[i][j][r] = 0.0f;

    __syncthreads();                      // koff table ready
    produce_chunk(0, sb, wp4, xb, koffs, prow, khalf, pswz);
    __syncthreads();

    for (int ch = 0; ch < KITERS; ++ch) {
        const uint32_t cur = sb + (uint32_t)(ch & 1) * BUF_STRIDE;
        if (ch + 1 < KITERS)
            produce_chunk(ch + 1, sb + (uint32_t)((ch + 1) & 1) * BUF_STRIDE,
                          wp4, xb, koffs, prow, khalf, pswz);
        mma_chunk(cur, acc, aRowOff, aKext, aSwz, bRowOff, bKext, bSwz);
        __syncthreads();
    }

    // epilogue: acc[am][an] rows co, co+8 ; cols gn, gn+1 (float2, same image)
    const int lane4 = lane >> 2, lane2 = (lane & 3) * 2;
    #pragma unroll
    for (int an = 0; an < 4; ++an) {
        const int gn = bn * 128 + wn * 32 + an * 8 + lane2;
        const int b2 = gn / NPIMG;
        const int r2 = gn - b2 * NPIMG;
        float* op = out + (size_t)b2 * OUTIMG + r2;
        #pragma unroll
        for (int am = 0; am < 4; ++am) {
            const int co = bm * 128 + wm * 64 + am * 16 + lane4;
            *(float2*)(op + (size_t)co * NPIMG) =
                make_float2(acc[am][an][0], acc[am][an][1]);
            *(float2*)(op + (size_t)(co + 8) * NPIMG) =
                make_float2(acc[am][an][2], acc[am][an][3]);
        }
    }
}

// ---------------------------------------------------------------------------
extern "C" void kernel_launch(void* const* d_in, const int* in_sizes, int n_in,
                              void* d_out, int out_size)
{
    const float* x = (const float*)d_in[0];   // [32,256,56,56]
    const float* w = (const float*)d_in[1];   // [512,256,3,3]
    float* out = (float*)d_out;               // [32,512,54,54]

    cudaFuncSetAttribute(conv_mma_kernel,
                         cudaFuncAttributeMaxDynamicSharedMemorySize, SMEM_BYTES);

    pack_x_kernel<<<25088, 256>>>(x);
    pack_w_kernel<<<1152, 256>>>(w);
    conv_mma_kernel<<<dim3(729, 4), 256, SMEM_BYTES>>>(out);
}